// round 1
// baseline (speedup 1.0000x reference)
#include <cuda_runtime.h>
#include <cuda_bf16.h>
#include <math.h>

// PyramidROIAlign: B=2, N=1000, C=256, pool 7x7, levels 2..5 with
// H,W = 256,128,64,32. Inputs (metadata order):
//   d_in[0] boxes      (B,N,4)  float32   [y1,x1,y2,x2] in [0,1]
//   d_in[1] image_meta (B,14)   float32   (meta[0,4],meta[0,5] = img H,W)
//   d_in[2] feat2      (B,256,256,C) float32
//   d_in[3] feat3      (B,128,128,C) float32
//   d_in[4] feat4      (B, 64, 64,C) float32
//   d_in[5] feat5      (B, 32, 32,C) float32
// Output: (B,N,7,7,C) float32.

#define POOLP 7
#define NPIX  (POOLP * POOLP)   // 49

__global__ __launch_bounds__(256, 8)
void pyramid_roi_align_kernel(const float* __restrict__ boxes,
                              const float* __restrict__ meta,
                              const float* __restrict__ f2,
                              const float* __restrict__ f3,
                              const float* __restrict__ f4,
                              const float* __restrict__ f5,
                              float* __restrict__ out,
                              int B, int N)
{
    const int roi = blockIdx.x;            // 0 .. B*N-1
    const int b   = roi / N;

    // ---- per-ROI scalars (redundant per thread; ~30 cheap ops) ----
    const float y1 = boxes[roi * 4 + 0];
    const float x1 = boxes[roi * 4 + 1];
    const float y2 = boxes[roi * 4 + 2];
    const float x2 = boxes[roi * 4 + 3];
    const float h  = y2 - y1;
    const float w  = x2 - x1;

    const float image_area = meta[4] * meta[5];          // image_meta[0,4]*[0,5]
    // lvl = log2( sqrt(h*w) / (224/sqrt(area)) )
    const float lvl = log2f(sqrtf(h * w) / (224.0f / sqrtf(image_area)));
    float rl = 4.0f + rintf(lvl);                        // jnp.round == rint (half-even)
    rl = fminf(fmaxf(rl, 2.0f), 5.0f);                   // clip in float, then cast
    const int level = (int)rl;

    const float* fm;
    int H;
    switch (level) {
        case 2:  fm = f2; H = 256; break;
        case 3:  fm = f3; H = 128; break;
        case 4:  fm = f4; H = 64;  break;
        default: fm = f5; H = 32;  break;
    }
    const int W = H;
    const int C4 = 64;                                   // 256 channels / 4

    const float4* __restrict__ fb =
        (const float4*)fm + (size_t)b * H * W * C4;
    float4* __restrict__ o4 =
        (float4*)out + (size_t)roi * NPIX * C4;

    const float Hm1 = (float)(H - 1);
    const float Wm1 = (float)(W - 1);
    const float sy  = h * Hm1 * (1.0f / (POOLP - 1));    // (y2-y1)*(H-1)/(ph-1)
    const float sx  = w * Wm1 * (1.0f / (POOLP - 1));
    const float by  = y1 * Hm1;
    const float bx  = x1 * Wm1;

    // Thread owns channel-quad c; walks pixels 4 at a time.
    const int c  = threadIdx.x & 63;                     // 0..63
    int       p  = threadIdx.x >> 6;                     // 0..3

    for (; p < NPIX; p += 4) {
        const int iy = p / POOLP;
        const int ix = p - iy * POOLP;

        // ---- sample coordinates (exact reference semantics) ----
        const float ys  = by + (float)iy * sy;
        const float xs  = bx + (float)ix * sx;
        const float y0f = floorf(ys);
        const float x0f = floorf(xs);
        int y0 = (int)y0f;  y0 = min(max(y0, 0), H - 1);
        int x0 = (int)x0f;  x0 = min(max(x0, 0), W - 1);
        const int y1i = min(y0 + 1, H - 1);
        const int x1i = min(x0 + 1, W - 1);
        const float fy = ys - y0f;                       // fraction from UNclipped floor
        const float fx = xs - x0f;

        const size_t r0 = (size_t)(y0  * W);
        const size_t r1 = (size_t)(y1i * W);

        const float4 tl = fb[(r0 + x0 ) * C4 + c];
        const float4 tr = fb[(r0 + x1i) * C4 + c];
        const float4 bl = fb[(r1 + x0 ) * C4 + c];
        const float4 br = fb[(r1 + x1i) * C4 + c];

        float4 r;
        {
            const float tx0 = tl.x + (tr.x - tl.x) * fx;
            const float tx1 = tl.y + (tr.y - tl.y) * fx;
            const float tx2 = tl.z + (tr.z - tl.z) * fx;
            const float tx3 = tl.w + (tr.w - tl.w) * fx;
            const float bx0 = bl.x + (br.x - bl.x) * fx;
            const float bx1 = bl.y + (br.y - bl.y) * fx;
            const float bx2 = bl.z + (br.z - bl.z) * fx;
            const float bx3 = bl.w + (br.w - bl.w) * fx;
            r.x = tx0 + (bx0 - tx0) * fy;
            r.y = tx1 + (bx1 - tx1) * fy;
            r.z = tx2 + (bx2 - tx2) * fy;
            r.w = tx3 + (bx3 - tx3) * fy;
        }
        o4[p * C4 + c] = r;
    }
}

extern "C" void kernel_launch(void* const* d_in, const int* in_sizes, int n_in,
                              void* d_out, int out_size)
{
    const float* boxes = (const float*)d_in[0];
    const float* meta  = (const float*)d_in[1];
    const float* f2    = (const float*)d_in[2];
    const float* f3    = (const float*)d_in[3];
    const float* f4    = (const float*)d_in[4];
    const float* f5    = (const float*)d_in[5];
    float* out = (float*)d_out;

    const int B = in_sizes[1] / 14;            // image_meta is (B,14)
    const int N = in_sizes[0] / (4 * B);       // boxes is (B,N,4)

    pyramid_roi_align_kernel<<<B * N, 256>>>(boxes, meta, f2, f3, f4, f5,
                                             out, B, N);
}

// round 3
// speedup vs baseline: 1.1241x; 1.1241x over previous
#include <cuda_runtime.h>
#include <cuda_bf16.h>
#include <math.h>

// PyramidROIAlign: B=2, N=1000, C=256, pool 7x7, levels 2..5 with
// H,W = 256,128,64,32.  Output: (B,N,7,7,C) float32.
//
// Mapping: one block per ROI (256 thr = 8 warps). Warp w owns pool pixels
// p = w, w+8, ... (<49). Within a warp, the 4 corner addresses are uniform;
// lane loads channel-quads `lane` and `lane+32` -> 8 independent LDG.128
// per pixel, x2 with unroll -> deep MLP to hide the ~260cyc L2-hit latency.

#define POOLP 7
#define NPIX  (POOLP * POOLP)   // 49

__global__ __launch_bounds__(256, 4)
void pyramid_roi_align_kernel(const float* __restrict__ boxes,
                              const float* __restrict__ meta,
                              const float* __restrict__ f2,
                              const float* __restrict__ f3,
                              const float* __restrict__ f4,
                              const float* __restrict__ f5,
                              float* __restrict__ out,
                              int B, int N)
{
    const int roi = blockIdx.x;            // 0 .. B*N-1
    const int b   = roi / N;

    // ---- per-ROI scalars (warp-uniform, cheap) ----
    const float y1 = boxes[roi * 4 + 0];
    const float x1 = boxes[roi * 4 + 1];
    const float y2 = boxes[roi * 4 + 2];
    const float x2 = boxes[roi * 4 + 3];
    const float h  = y2 - y1;
    const float w  = x2 - x1;

    const float image_area = meta[4] * meta[5];          // image_meta[0,4]*[0,5]
    const float lvl = log2f(sqrtf(h * w) / (224.0f / sqrtf(image_area)));
    float rl = 4.0f + rintf(lvl);                        // jnp.round == rint
    rl = fminf(fmaxf(rl, 2.0f), 5.0f);
    const int level = (int)rl;

    const float* fm;
    int H;
    switch (level) {
        case 2:  fm = f2; H = 256; break;
        case 3:  fm = f3; H = 128; break;
        case 4:  fm = f4; H = 64;  break;
        default: fm = f5; H = 32;  break;
    }
    const int W  = H;
    const int C4 = 64;                                   // 256 ch / 4

    const float4* __restrict__ fb =
        (const float4*)fm + (size_t)b * H * W * C4;
    float4* __restrict__ o4 =
        (float4*)out + (size_t)roi * NPIX * C4;

    const float Hm1 = (float)(H - 1);
    const float Wm1 = (float)(W - 1);
    const float sy  = h * Hm1 * (1.0f / (POOLP - 1));    // (y2-y1)*(H-1)/(ph-1)
    const float sx  = w * Wm1 * (1.0f / (POOLP - 1));
    const float by  = y1 * Hm1;
    const float bx  = x1 * Wm1;

    const int lane = threadIdx.x & 31;                   // channel quads lane, lane+32
    const int wrp  = threadIdx.x >> 5;                   // pool pixel start (0..7)

    #pragma unroll 2
    for (int p = wrp; p < NPIX; p += 8) {
        const int iy = p / POOLP;                        // const-div -> mul
        const int ix = p - iy * POOLP;

        // ---- sample coordinates (exact reference semantics) ----
        const float ys  = by + (float)iy * sy;
        const float xs  = bx + (float)ix * sx;
        const float y0f = floorf(ys);
        const float x0f = floorf(xs);
        int y0 = (int)y0f;  y0 = min(max(y0, 0), H - 1);
        int x0 = (int)x0f;  x0 = min(max(x0, 0), W - 1);
        const int y1i = min(y0 + 1, H - 1);
        const int x1i = min(x0 + 1, W - 1);
        const float fy = ys - y0f;                       // frac from UNclipped floor
        const float fx = xs - x0f;

        // warp-uniform corner base offsets (in float4 units)
        const int off_tl = (y0  * W + x0 ) * C4;
        const int off_tr = (y0  * W + x1i) * C4;
        const int off_bl = (y1i * W + x0 ) * C4;
        const int off_br = (y1i * W + x1i) * C4;

        // 8 independent loads (4 corners x 2 channel halves)
        const float4 tl0 = fb[off_tl + lane];
        const float4 tr0 = fb[off_tr + lane];
        const float4 bl0 = fb[off_bl + lane];
        const float4 br0 = fb[off_br + lane];
        const float4 tl1 = fb[off_tl + lane + 32];
        const float4 tr1 = fb[off_tr + lane + 32];
        const float4 bl1 = fb[off_bl + lane + 32];
        const float4 br1 = fb[off_br + lane + 32];

        float4 r0, r1;
        {
            float t, bo;
            t  = tl0.x + (tr0.x - tl0.x) * fx;  bo = bl0.x + (br0.x - bl0.x) * fx;  r0.x = t + (bo - t) * fy;
            t  = tl0.y + (tr0.y - tl0.y) * fx;  bo = bl0.y + (br0.y - bl0.y) * fx;  r0.y = t + (bo - t) * fy;
            t  = tl0.z + (tr0.z - tl0.z) * fx;  bo = bl0.z + (br0.z - bl0.z) * fx;  r0.z = t + (bo - t) * fy;
            t  = tl0.w + (tr0.w - tl0.w) * fx;  bo = bl0.w + (br0.w - bl0.w) * fx;  r0.w = t + (bo - t) * fy;
            t  = tl1.x + (tr1.x - tl1.x) * fx;  bo = bl1.x + (br1.x - bl1.x) * fx;  r1.x = t + (bo - t) * fy;
            t  = tl1.y + (tr1.y - tl1.y) * fx;  bo = bl1.y + (br1.y - bl1.y) * fx;  r1.y = t + (bo - t) * fy;
            t  = tl1.z + (tr1.z - tl1.z) * fx;  bo = bl1.z + (br1.z - bl1.z) * fx;  r1.z = t + (bo - t) * fy;
            t  = tl1.w + (tr1.w - tl1.w) * fx;  bo = bl1.w + (br1.w - bl1.w) * fx;  r1.w = t + (bo - t) * fy;
        }
        o4[p * C4 + lane]      = r0;
        o4[p * C4 + lane + 32] = r1;
    }
}

extern "C" void kernel_launch(void* const* d_in, const int* in_sizes, int n_in,
                              void* d_out, int out_size)
{
    const float* boxes = (const float*)d_in[0];
    const float* meta  = (const float*)d_in[1];
    const float* f2    = (const float*)d_in[2];
    const float* f3    = (const float*)d_in[3];
    const float* f4    = (const float*)d_in[4];
    const float* f5    = (const float*)d_in[5];
    float* out = (float*)d_out;

    const int B = in_sizes[1] / 14;            // image_meta is (B,14)
    const int N = in_sizes[0] / (4 * B);       // boxes is (B,N,4)

    pyramid_roi_align_kernel<<<B * N, 256>>>(boxes, meta, f2, f3, f4, f5,
                                             out, B, N);
}